// round 8
// baseline (speedup 1.0000x reference)
#include <cuda_runtime.h>
#include <cuda_bf16.h>
#include <math.h>

#define SEQ   2048
#define HDIM  2048
#define NH    16
#define QLR   1536
#define KVLR  512
#define NOPE  128
#define ROPEDIM 64
#define VHD   128
#define QHD   192   // NOPE + ROPE

// ---------------- scratch arena (no allocations allowed) ----------------
#define OFF_QLAT    0
#define OFF_KVLATPE (OFF_QLAT    + SEQ*QLR)
#define OFF_KVLAT   (OFF_KVLATPE + SEQ*(KVLR+ROPEDIM))
#define OFF_KPE     (OFF_KVLAT   + SEQ*KVLR)
#define OFF_Q       (OFF_KPE     + SEQ*ROPEDIM)
#define OFF_KV      (OFF_Q       + SEQ*NH*QHD)
#define OFF_ATTN    (OFF_KV      + SEQ*NH*(NOPE+VHD))
#define OFF_SCORES  (OFF_ATTN    + SEQ*NH*VHD)
#define SCRATCH_TOTAL ((size_t)OFF_SCORES + (size_t)NH*SEQ*SEQ)

__device__ float g_scratch[SCRATCH_TOTAL];

// ---------------- textbook NT SGEMM: C[M,N] = A[M,K] @ B[N,K]^T ----------------
__global__ void sgemm_nt16(const float* __restrict__ A,
                           const float* __restrict__ B,
                           float* __restrict__ C,
                           int M, int N, int K) {
    __shared__ float As[16][16];
    __shared__ float Bs[16][16];
    const int tx = threadIdx.x;
    const int ty = threadIdx.y;
    const int row = blockIdx.y * 16 + ty;
    const int col = blockIdx.x * 16 + tx;

    float acc = 0.0f;
    for (int k0 = 0; k0 < K; k0 += 16) {
        As[ty][tx] = (row < M) ? A[(size_t)row * K + k0 + tx] : 0.0f;
        int bn = blockIdx.x * 16 + ty;
        Bs[tx][ty] = (bn < N) ? B[(size_t)bn * K + k0 + tx] : 0.0f;
        __syncthreads();
#pragma unroll
        for (int k = 0; k < 16; k++)
            acc += As[ty][k] * Bs[k][tx];
        __syncthreads();
    }
    if (row < M && col < N) C[(size_t)row * N + col] = acc;
}

// ---------------- RMS norms (pure-smem serial reduction) ----------------
__global__ __launch_bounds__(256) void rms_q_kernel(float* __restrict__ x,
                                                    const float* __restrict__ w) {
    __shared__ float sbuf[256];
    const int row = blockIdx.x;
    float* p = x + (size_t)row * QLR;
    float ss = 0.0f;
    for (int d = threadIdx.x; d < QLR; d += 256) { float v = p[d]; ss += v * v; }
    sbuf[threadIdx.x] = ss;
    __syncthreads();
    if (threadIdx.x == 0) {
        float r = 0.0f;
        for (int i = 0; i < 256; i++) r += sbuf[i];
        sbuf[0] = r;
    }
    __syncthreads();
    const float inv = rsqrtf(sbuf[0] * (1.0f / QLR) + 1e-6f);
    for (int d = threadIdx.x; d < QLR; d += 256) p[d] = p[d] * inv * w[d];
}

__global__ __launch_bounds__(256) void rms_kv_kernel(const float* __restrict__ xin,
                                                     const float* __restrict__ w,
                                                     float* __restrict__ xout) {
    __shared__ float sbuf[256];
    const int row = blockIdx.x;
    const float* p = xin + (size_t)row * (KVLR + ROPEDIM);
    float ss = 0.0f;
    for (int d = threadIdx.x; d < KVLR; d += 256) { float v = p[d]; ss += v * v; }
    sbuf[threadIdx.x] = ss;
    __syncthreads();
    if (threadIdx.x == 0) {
        float r = 0.0f;
        for (int i = 0; i < 256; i++) r += sbuf[i];
        sbuf[0] = r;
    }
    __syncthreads();
    const float inv = rsqrtf(sbuf[0] * (1.0f / KVLR) + 1e-6f);
    float* o = xout + (size_t)row * KVLR;
    for (int d = threadIdx.x; d < KVLR; d += 256) o[d] = p[d] * inv * w[d];
}

// ---------------- RoPE: half-split pairing, NEGATED rotation sign ----------------
// pair (j, j+32), angle t * 10000^(-j/32), rotation by -theta:
//   y0 = x0*cos + x1*sin
//   y1 = x1*cos - x0*sin
__device__ __forceinline__ float rope_invfreq(int j) {
    return exp2f(-(float)j * (13.287712379549449f / 32.0f));  // 10000^(-j/32)
}

__global__ void rope_q_kernel(float* __restrict__ q) {
    const int t = blockIdx.x;
    const int h = threadIdx.x >> 5;     // 0..15
    const int j = threadIdx.x & 31;     // pair index 0..31
    float* base = q + (size_t)t * (NH * QHD) + h * QHD + NOPE;
    float c, s;
    sincosf((float)t * rope_invfreq(j), &c, &s);
    const float x0 = base[j];
    const float x1 = base[j + 32];
    base[j]      = x0 * c + x1 * s;
    base[j + 32] = x1 * c - x0 * s;
}

__global__ void rope_k_kernel(const float* __restrict__ kvlatpe, float* __restrict__ kpe) {
    const int t = blockIdx.x;
    const int j = threadIdx.x;   // 0..31
    const float* base = kvlatpe + (size_t)t * (KVLR + ROPEDIM) + KVLR;
    float c, s;
    sincosf((float)t * rope_invfreq(j), &c, &s);
    const float x0 = base[j];
    const float x1 = base[j + 32];
    kpe[(size_t)t * ROPEDIM + j]      = x0 * c + x1 * s;
    kpe[(size_t)t * ROPEDIM + j + 32] = x1 * c - x0 * s;
}

// ---------------- attention stage 1: scores = scale * Q K^T (causal tiles only)
__global__ __launch_bounds__(256) void score_kernel(const float* __restrict__ q,
                                                    const float* __restrict__ kv,
                                                    const float* __restrict__ kpe,
                                                    float* __restrict__ sc) {
    const int kb = blockIdx.x, qb = blockIdx.y, h = blockIdx.z;
    if (kb > qb) return;
    __shared__ float Qt[16 * 193];
    __shared__ float Kt[16 * 193];
    const int tx = threadIdx.x, ty = threadIdx.y;
    const int tid = ty * 16 + tx;
    const float scale = 0.07216878364870323f;  // 192^-0.5

    for (int idx = tid; idx < 16 * 192; idx += 256) {
        int r = idx / 192, d = idx - r * 192;
        Qt[r * 193 + d] = q[(size_t)(qb * 16 + r) * (NH * QHD) + h * QHD + d] * scale;
        Kt[r * 193 + d] = (d < NOPE)
            ? kv[(size_t)(kb * 16 + r) * (NH * (NOPE + VHD)) + h * (NOPE + VHD) + d]
            : kpe[(size_t)(kb * 16 + r) * ROPEDIM + (d - NOPE)];
    }
    __syncthreads();

    float acc = 0.0f;
#pragma unroll 8
    for (int d = 0; d < 192; d++)
        acc += Qt[ty * 193 + d] * Kt[tx * 193 + d];

    sc[((size_t)h * SEQ + (qb * 16 + ty)) * SEQ + kb * 16 + tx] = acc;
}

// ---------------- attention stage 2: in-place causal row softmax ----------------
__global__ __launch_bounds__(256) void softmax_kernel(float* __restrict__ sc) {
    const int qpos = blockIdx.x, h = blockIdx.y;
    float* row = sc + ((size_t)h * SEQ + qpos) * SEQ;
    const int n = qpos + 1;
    const int tid = threadIdx.x;
    __shared__ float sbuf[256];
    __shared__ float bc;

    float m = -1e30f;
    for (int k = tid; k < n; k += 256) m = fmaxf(m, row[k]);
    sbuf[tid] = m;
    __syncthreads();
    if (tid == 0) {
        float r = -1e30f;
        for (int i = 0; i < 256; i++) r = fmaxf(r, sbuf[i]);
        bc = r;
    }
    __syncthreads();
    const float mx = bc;
    __syncthreads();

    float l = 0.0f;
    for (int k = tid; k < n; k += 256) l += __expf(row[k] - mx);
    sbuf[tid] = l;
    __syncthreads();
    if (tid == 0) {
        float r = 0.0f;
        for (int i = 0; i < 256; i++) r += sbuf[i];
        bc = r;
    }
    __syncthreads();
    const float inv = 1.0f / bc;

    for (int k = tid; k < n; k += 256) row[k] = __expf(row[k] - mx) * inv;
    for (int k = n + tid; k < SEQ; k += 256) row[k] = 0.0f;
}

// ---------------- attention stage 3: attn = P @ V ----------------
#define PV_SMEM_FLOATS (64 * 65 + 64 * 128)
#define PV_SMEM_BYTES  (PV_SMEM_FLOATS * 4)
__global__ __launch_bounds__(256) void pv_kernel(const float* __restrict__ probs,
                                                 const float* __restrict__ kv,
                                                 float* __restrict__ attn) {
    extern __shared__ __align__(16) float sm[];
    float* Ps = sm;            // [64][65]
    float* Vs = sm + 64 * 65;  // [64][128]

    const int tid = threadIdx.x;
    const int tx = tid & 15;
    const int ty = tid >> 4;
    const int qb = blockIdx.x;
    const int h  = blockIdx.y;
    const int qbase = qb * 64;

    float acc[4][8];
#pragma unroll
    for (int i = 0; i < 4; i++)
#pragma unroll
        for (int j = 0; j < 8; j++) acc[i][j] = 0.0f;

    for (int kt = 0; kt <= qb; kt++) {
        const int kbase = kt * 64;
        __syncthreads();
        for (int idx = tid; idx < 64 * 64; idx += 256) {
            int r = idx >> 6, c = idx & 63;
            Ps[r * 65 + c] = probs[((size_t)h * SEQ + qbase + r) * SEQ + kbase + c];
        }
        for (int idx = tid; idx < 64 * 128; idx += 256) {
            int c = idx >> 7, d = idx & 127;
            Vs[c * 128 + d] =
                kv[(size_t)(kbase + c) * (NH * (NOPE + VHD)) + h * (NOPE + VHD) + NOPE + d];
        }
        __syncthreads();

#pragma unroll 2
        for (int kk = 0; kk < 64; kk++) {
            const float4 v0 = *(const float4*)&Vs[kk * 128 + tx * 8];
            const float4 v1 = *(const float4*)&Vs[kk * 128 + tx * 8 + 4];
#pragma unroll
            for (int i = 0; i < 4; i++) {
                float p = Ps[(ty * 4 + i) * 65 + kk];
                acc[i][0] += p * v0.x; acc[i][1] += p * v0.y;
                acc[i][2] += p * v0.z; acc[i][3] += p * v0.w;
                acc[i][4] += p * v1.x; acc[i][5] += p * v1.y;
                acc[i][6] += p * v1.z; acc[i][7] += p * v1.w;
            }
        }
    }

#pragma unroll
    for (int i = 0; i < 4; i++) {
        int t = qbase + ty * 4 + i;
        float* o = attn + (size_t)t * (NH * VHD) + h * VHD + tx * 8;
#pragma unroll
        for (int j = 0; j < 8; j++) o[j] = acc[i][j];
    }
}

// ---------------- launch ----------------
extern "C" void kernel_launch(void* const* d_in, const int* in_sizes, int n_in,
                              void* d_out, int out_size) {
    const float *hidden = nullptr, *q_a_w = nullptr, *q_a_ln_w = nullptr, *q_b_w = nullptr,
                *kv_a_w = nullptr, *kv_a_ln_w = nullptr, *kv_b_w = nullptr, *o_w = nullptr;
    for (int i = 0; i < n_in; i++) {
        const float* p = (const float*)d_in[i];
        switch (in_sizes[i]) {
            case QLR * HDIM:                q_a_w = p;    break;  // 3145728
            case QLR:                       q_a_ln_w = p; break;  // 1536
            case NH * QHD * QLR:            q_b_w = p;    break;  // 4718592
            case (KVLR + ROPEDIM) * HDIM:   kv_a_w = p;   break;  // 1179648
            case KVLR:                      kv_a_ln_w = p;break;  // 512
            case NH * (NOPE + VHD) * KVLR:  kv_b_w = p;   break;  // 2097152
            case SEQ * HDIM:  if (!hidden) hidden = p; else o_w = p; break; // 4194304 x2
        }
    }
    float* out = (float*)d_out;

    float* base = nullptr;
    cudaGetSymbolAddress((void**)&base, g_scratch);
    float* qlat    = base + OFF_QLAT;
    float* kvlatpe = base + OFF_KVLATPE;
    float* kvlat   = base + OFF_KVLAT;
    float* kpe     = base + OFF_KPE;
    float* qbuf    = base + OFF_Q;
    float* kvbuf   = base + OFF_KV;
    float* attnbuf = base + OFF_ATTN;
    float* scores  = base + OFF_SCORES;

    cudaFuncSetAttribute(pv_kernel, cudaFuncAttributeMaxDynamicSharedMemorySize,
                         PV_SMEM_BYTES);

    dim3 t16(16, 16);
    sgemm_nt16<<<dim3(QLR / 16, SEQ / 16), t16>>>(hidden, q_a_w, qlat, SEQ, QLR, HDIM);
    sgemm_nt16<<<dim3((KVLR + ROPEDIM) / 16, SEQ / 16), t16>>>(hidden, kv_a_w, kvlatpe,
                                                               SEQ, KVLR + ROPEDIM, HDIM);
    rms_q_kernel<<<SEQ, 256>>>(qlat, q_a_ln_w);
    rms_kv_kernel<<<SEQ, 256>>>(kvlatpe, kv_a_ln_w, kvlat);
    rope_k_kernel<<<SEQ, 32>>>(kvlatpe, kpe);
    sgemm_nt16<<<dim3((NH * QHD) / 16, SEQ / 16), t16>>>(qlat, q_b_w, qbuf, SEQ, NH * QHD, QLR);
    sgemm_nt16<<<dim3((NH * (NOPE + VHD)) / 16, SEQ / 16), t16>>>(kvlat, kv_b_w, kvbuf,
                                                                  SEQ, NH * (NOPE + VHD), KVLR);
    rope_q_kernel<<<SEQ, 512>>>(qbuf);

    score_kernel<<<dim3(SEQ / 16, SEQ / 16, NH), dim3(16, 16)>>>(qbuf, kvbuf, kpe, scores);
    softmax_kernel<<<dim3(SEQ, NH), 256>>>(scores);
    pv_kernel<<<dim3(SEQ / 64, NH), 256, PV_SMEM_BYTES>>>(scores, kvbuf, attnbuf);

    sgemm_nt16<<<dim3(HDIM / 16, SEQ / 16), t16>>>(attnbuf, o_w, out, SEQ, HDIM, NH * VHD);
}

// round 9
// speedup vs baseline: 2.4919x; 2.4919x over previous
#include <cuda_runtime.h>
#include <cuda_bf16.h>
#include <math.h>

#define SEQ   2048
#define HDIM  2048
#define NH    16
#define QLR   1536
#define KVLR  512
#define NOPE  128
#define ROPEDIM 64
#define VHD   128
#define QHD   192   // NOPE + ROPE

// ---------------- scratch arena (no allocations allowed) ----------------
#define OFF_QLAT    0
#define OFF_KVLATPE (OFF_QLAT    + SEQ*QLR)
#define OFF_KVLAT   (OFF_KVLATPE + SEQ*(KVLR+ROPEDIM))
#define OFF_KPE     (OFF_KVLAT   + SEQ*KVLR)
#define OFF_Q       (OFF_KPE     + SEQ*ROPEDIM)
#define OFF_KV      (OFF_Q       + SEQ*NH*QHD)
#define OFF_ATTN    (OFF_KV      + SEQ*NH*(NOPE+VHD))
#define SCRATCH_TOTAL (OFF_ATTN  + SEQ*NH*VHD)

__device__ float g_scratch[SCRATCH_TOTAL];

// ---------------- fast NT SGEMM: C[M,N] = A[M,K] @ B[N,K]^T ----------------
// 128x128 block, BK=8, 256 threads, 8x8 microtile. (Cross-validated rounds 1-2.)
__global__ __launch_bounds__(256) void sgemm_nt(const float* __restrict__ A,
                                                const float* __restrict__ B,
                                                float* __restrict__ C,
                                                int M, int N, int K) {
    __shared__ __align__(16) float As[8 * 132];
    __shared__ __align__(16) float Bs[8 * 132];

    const int tid = threadIdx.x;
    const int tx  = tid & 15;
    const int ty  = tid >> 4;
    const int row0 = blockIdx.y * 128;
    const int col0 = blockIdx.x * 128;

    float acc[8][8];
#pragma unroll
    for (int i = 0; i < 8; i++)
#pragma unroll
        for (int j = 0; j < 8; j++) acc[i][j] = 0.0f;

    const int lr = tid >> 1;
    const int lk = (tid & 1) * 4;
    const bool aval = (row0 + lr) < M;
    const bool bval = (col0 + lr) < N;
    const float* Aptr = A + (size_t)(row0 + lr) * K + lk;
    const float* Bptr = B + (size_t)(col0 + lr) * K + lk;

    for (int k0 = 0; k0 < K; k0 += 8) {
        float4 av = aval ? *(const float4*)(Aptr + k0) : make_float4(0.f, 0.f, 0.f, 0.f);
        float4 bv = bval ? *(const float4*)(Bptr + k0) : make_float4(0.f, 0.f, 0.f, 0.f);
        As[(lk + 0) * 132 + lr] = av.x;
        As[(lk + 1) * 132 + lr] = av.y;
        As[(lk + 2) * 132 + lr] = av.z;
        As[(lk + 3) * 132 + lr] = av.w;
        Bs[(lk + 0) * 132 + lr] = bv.x;
        Bs[(lk + 1) * 132 + lr] = bv.y;
        Bs[(lk + 2) * 132 + lr] = bv.z;
        Bs[(lk + 3) * 132 + lr] = bv.w;
        __syncthreads();

#pragma unroll
        for (int kk = 0; kk < 8; kk++) {
            const float4 a0 = *(const float4*)&As[kk * 132 + ty * 8];
            const float4 a1 = *(const float4*)&As[kk * 132 + ty * 8 + 4];
            const float4 b0 = *(const float4*)&Bs[kk * 132 + tx * 8];
            const float4 b1 = *(const float4*)&Bs[kk * 132 + tx * 8 + 4];
            float a[8] = {a0.x, a0.y, a0.z, a0.w, a1.x, a1.y, a1.z, a1.w};
            float b[8] = {b0.x, b0.y, b0.z, b0.w, b1.x, b1.y, b1.z, b1.w};
#pragma unroll
            for (int i = 0; i < 8; i++)
#pragma unroll
                for (int j = 0; j < 8; j++) acc[i][j] += a[i] * b[j];
        }
        __syncthreads();
    }

#pragma unroll
    for (int i = 0; i < 8; i++) {
        int r = row0 + ty * 8 + i;
        if (r >= M) continue;
#pragma unroll
        for (int j = 0; j < 8; j++) {
            int c = col0 + tx * 8 + j;
            if (c < N) C[(size_t)r * N + c] = acc[i][j];
        }
    }
}

// ---------------- RMS norms (pure-smem serial reduction; negligible time) ------
__global__ __launch_bounds__(256) void rms_q_kernel(float* __restrict__ x,
                                                    const float* __restrict__ w) {
    __shared__ float sbuf[256];
    const int row = blockIdx.x;
    float* p = x + (size_t)row * QLR;
    float ss = 0.0f;
    for (int d = threadIdx.x; d < QLR; d += 256) { float v = p[d]; ss += v * v; }
    sbuf[threadIdx.x] = ss;
    __syncthreads();
    if (threadIdx.x == 0) {
        float r = 0.0f;
        for (int i = 0; i < 256; i++) r += sbuf[i];
        sbuf[0] = r;
    }
    __syncthreads();
    const float inv = rsqrtf(sbuf[0] * (1.0f / QLR) + 1e-6f);
    for (int d = threadIdx.x; d < QLR; d += 256) p[d] = p[d] * inv * w[d];
}

__global__ __launch_bounds__(256) void rms_kv_kernel(const float* __restrict__ xin,
                                                     const float* __restrict__ w,
                                                     float* __restrict__ xout) {
    __shared__ float sbuf[256];
    const int row = blockIdx.x;
    const float* p = xin + (size_t)row * (KVLR + ROPEDIM);
    float ss = 0.0f;
    for (int d = threadIdx.x; d < KVLR; d += 256) { float v = p[d]; ss += v * v; }
    sbuf[threadIdx.x] = ss;
    __syncthreads();
    if (threadIdx.x == 0) {
        float r = 0.0f;
        for (int i = 0; i < 256; i++) r += sbuf[i];
        sbuf[0] = r;
    }
    __syncthreads();
    const float inv = rsqrtf(sbuf[0] * (1.0f / KVLR) + 1e-6f);
    float* o = xout + (size_t)row * KVLR;
    for (int d = threadIdx.x; d < KVLR; d += 256) o[d] = p[d] * inv * w[d];
}

// ---------------- RoPE: half-split pairing, NEGATED rotation sign (validated R8)
__device__ __forceinline__ float rope_invfreq(int j) {
    return exp2f(-(float)j * (13.287712379549449f / 32.0f));  // 10000^(-j/32)
}

__global__ void rope_q_kernel(float* __restrict__ q) {
    const int t = blockIdx.x;
    const int h = threadIdx.x >> 5;     // 0..15
    const int j = threadIdx.x & 31;     // pair index 0..31
    float* base = q + (size_t)t * (NH * QHD) + h * QHD + NOPE;
    float c, s;
    sincosf((float)t * rope_invfreq(j), &c, &s);
    const float x0 = base[j];
    const float x1 = base[j + 32];
    base[j]      = x0 * c + x1 * s;
    base[j + 32] = x1 * c - x0 * s;
}

__global__ void rope_k_kernel(const float* __restrict__ kvlatpe, float* __restrict__ kpe) {
    const int t = blockIdx.x;
    const int j = threadIdx.x;   // 0..31
    const float* base = kvlatpe + (size_t)t * (KVLR + ROPEDIM) + KVLR;
    float c, s;
    sincosf((float)t * rope_invfreq(j), &c, &s);
    const float x0 = base[j];
    const float x1 = base[j + 32];
    kpe[(size_t)t * ROPEDIM + j]      = x0 * c + x1 * s;
    kpe[(size_t)t * ROPEDIM + j + 32] = x1 * c - x0 * s;
}

// ---------------- Flash attention (fp32, causal, smem softmax) ----------------
// Cross-validated vs materialized pipeline (rounds 2/3 identical results).
// smem: Qs[192][65] + Ks[192][65] + Vs[64][128] + Ps[64][65] + m/l/corr[64]
#define FLASH_SMEM_FLOATS (192 * 65 * 2 + 64 * 128 + 64 * 65 + 3 * 64)
#define FLASH_SMEM_BYTES  (FLASH_SMEM_FLOATS * 4)

__global__ __launch_bounds__(256) void flash_kernel(const float* __restrict__ q,
                                                    const float* __restrict__ kv,
                                                    const float* __restrict__ kpe,
                                                    float* __restrict__ attn) {
    extern __shared__ __align__(16) float sm[];
    float* Qs  = sm;                   // [192][65] d-major
    float* Ks  = sm + 192 * 65;        // [192][65] d-major
    float* Vs  = Ks + 192 * 65;        // [64][128]
    float* Ps  = Vs + 64 * 128;        // [64][65]
    float* m_s = Ps + 64 * 65;         // [64]
    float* l_s = m_s + 64;             // [64]
    float* c_s = l_s + 64;             // [64]

    const int tid = threadIdx.x;
    const int tx = tid & 15;
    const int ty = tid >> 4;
    const int qb = blockIdx.x;
    const int h  = blockIdx.y;
    const int qbase = qb * 64;
    const float scale = 0.07216878364870323f;  // 192^-0.5

    for (int idx = tid; idx < 64 * 192; idx += 256) {
        int r = idx / 192, d = idx - r * 192;
        Qs[d * 65 + r] = q[(size_t)(qbase + r) * (NH * QHD) + h * QHD + d] * scale;
    }
    if (tid < 64) { m_s[tid] = -1e30f; l_s[tid] = 0.0f; }

    float acc[4][8];
#pragma unroll
    for (int i = 0; i < 4; i++)
#pragma unroll
        for (int j = 0; j < 8; j++) acc[i][j] = 0.0f;

    for (int kb = 0; kb <= qb; kb++) {
        const int kbase = kb * 64;
        __syncthreads();
        for (int idx = tid; idx < 64 * 192; idx += 256) {
            int c = idx / 192, d = idx - c * 192;
            float v = (d < NOPE)
                ? kv[(size_t)(kbase + c) * (NH * (NOPE + VHD)) + h * (NOPE + VHD) + d]
                : kpe[(size_t)(kbase + c) * ROPEDIM + (d - NOPE)];
            Ks[d * 65 + c] = v;
        }
        for (int idx = tid; idx < 64 * 128; idx += 256) {
            int c = idx >> 7, d = idx & 127;
            Vs[c * 128 + d] =
                kv[(size_t)(kbase + c) * (NH * (NOPE + VHD)) + h * (NOPE + VHD) + NOPE + d];
        }
        __syncthreads();

        // S = Q K^T  (64x64 over 192 dims)
        float s[4][4];
#pragma unroll
        for (int i = 0; i < 4; i++)
#pragma unroll
            for (int j = 0; j < 4; j++) s[i][j] = 0.0f;

#pragma unroll 4
        for (int d = 0; d < 192; d++) {
            float a0 = Qs[d * 65 + ty * 4 + 0];
            float a1 = Qs[d * 65 + ty * 4 + 1];
            float a2 = Qs[d * 65 + ty * 4 + 2];
            float a3 = Qs[d * 65 + ty * 4 + 3];
            float b0 = Ks[d * 65 + tx * 4 + 0];
            float b1 = Ks[d * 65 + tx * 4 + 1];
            float b2 = Ks[d * 65 + tx * 4 + 2];
            float b3 = Ks[d * 65 + tx * 4 + 3];
            s[0][0] += a0 * b0; s[0][1] += a0 * b1; s[0][2] += a0 * b2; s[0][3] += a0 * b3;
            s[1][0] += a1 * b0; s[1][1] += a1 * b1; s[1][2] += a1 * b2; s[1][3] += a1 * b3;
            s[2][0] += a2 * b0; s[2][1] += a2 * b1; s[2][2] += a2 * b2; s[2][3] += a2 * b3;
            s[3][0] += a3 * b0; s[3][1] += a3 * b1; s[3][2] += a3 * b2; s[3][3] += a3 * b3;
        }

        if (kb == qb) {   // causal mask only on diagonal tile
#pragma unroll
            for (int i = 0; i < 4; i++)
#pragma unroll
                for (int j = 0; j < 4; j++)
                    if (tx * 4 + j > ty * 4 + i) s[i][j] = -1e30f;
        }

#pragma unroll
        for (int i = 0; i < 4; i++)
#pragma unroll
            for (int j = 0; j < 4; j++)
                Ps[(ty * 4 + i) * 65 + tx * 4 + j] = s[i][j];
        __syncthreads();

        // per-row online softmax in smem: one thread per row
        if (tid < 64) {
            const int row = tid;
            float mx = -1e30f;
            for (int c = 0; c < 64; c++) mx = fmaxf(mx, Ps[row * 65 + c]);
            float mold = m_s[row];
            float mnew = fmaxf(mold, mx);
            float corr = __expf(mold - mnew);
            float rs = 0.0f;
            for (int c = 0; c < 64; c++) {
                float e = __expf(Ps[row * 65 + c] - mnew);
                Ps[row * 65 + c] = e;
                rs += e;
            }
            l_s[row] = l_s[row] * corr + rs;
            m_s[row] = mnew;
            c_s[row] = corr;
        }
        __syncthreads();

        // acc = acc * corr + P @ V
#pragma unroll
        for (int i = 0; i < 4; i++) {
            float corr = c_s[ty * 4 + i];
#pragma unroll
            for (int j = 0; j < 8; j++) acc[i][j] *= corr;
        }
#pragma unroll 2
        for (int kk = 0; kk < 64; kk++) {
            const float4 v0 = *(const float4*)&Vs[kk * 128 + tx * 8];
            const float4 v1 = *(const float4*)&Vs[kk * 128 + tx * 8 + 4];
#pragma unroll
            for (int i = 0; i < 4; i++) {
                float p = Ps[(ty * 4 + i) * 65 + kk];
                acc[i][0] += p * v0.x; acc[i][1] += p * v0.y;
                acc[i][2] += p * v0.z; acc[i][3] += p * v0.w;
                acc[i][4] += p * v1.x; acc[i][5] += p * v1.y;
                acc[i][6] += p * v1.z; acc[i][7] += p * v1.w;
            }
        }
    }

#pragma unroll
    for (int i = 0; i < 4; i++) {
        float inv = 1.0f / l_s[ty * 4 + i];
        int t = qbase + ty * 4 + i;
        float* o = attn + (size_t)t * (NH * VHD) + h * VHD + tx * 8;
#pragma unroll
        for (int j = 0; j < 8; j++) o[j] = acc[i][j] * inv;
    }
}

// ---------------- launch ----------------
extern "C" void kernel_launch(void* const* d_in, const int* in_sizes, int n_in,
                              void* d_out, int out_size) {
    const float *hidden = nullptr, *q_a_w = nullptr, *q_a_ln_w = nullptr, *q_b_w = nullptr,
                *kv_a_w = nullptr, *kv_a_ln_w = nullptr, *kv_b_w = nullptr, *o_w = nullptr;
    for (int i = 0; i < n_in; i++) {
        const float* p = (const float*)d_in[i];
        switch (in_sizes[i]) {
            case QLR * HDIM:                q_a_w = p;    break;  // 3145728
            case QLR:                       q_a_ln_w = p; break;  // 1536
            case NH * QHD * QLR:            q_b_w = p;    break;  // 4718592
            case (KVLR + ROPEDIM) * HDIM:   kv_a_w = p;   break;  // 1179648
            case KVLR:                      kv_a_ln_w = p;break;  // 512
            case NH * (NOPE + VHD) * KVLR:  kv_b_w = p;   break;  // 2097152
            case SEQ * HDIM:  if (!hidden) hidden = p; else o_w = p; break; // 4194304 x2
        }
    }
    float* out = (float*)d_out;

    float* base = nullptr;
    cudaGetSymbolAddress((void**)&base, g_scratch);
    float* qlat    = base + OFF_QLAT;
    float* kvlatpe = base + OFF_KVLATPE;
    float* kvlat   = base + OFF_KVLAT;
    float* kpe     = base + OFF_KPE;
    float* qbuf    = base + OFF_Q;
    float* kvbuf   = base + OFF_KV;
    float* attnbuf = base + OFF_ATTN;

    cudaFuncSetAttribute(flash_kernel, cudaFuncAttributeMaxDynamicSharedMemorySize,
                         FLASH_SMEM_BYTES);

    sgemm_nt<<<dim3(QLR / 128, SEQ / 128), 256>>>(hidden, q_a_w, qlat, SEQ, QLR, HDIM);
    sgemm_nt<<<dim3((KVLR + ROPEDIM + 127) / 128, SEQ / 128), 256>>>(hidden, kv_a_w, kvlatpe,
                                                                     SEQ, KVLR + ROPEDIM, HDIM);
    rms_q_kernel<<<SEQ, 256>>>(qlat, q_a_ln_w);
    rms_kv_kernel<<<SEQ, 256>>>(kvlatpe, kv_a_ln_w, kvlat);
    rope_k_kernel<<<SEQ, 32>>>(kvlatpe, kpe);
    sgemm_nt<<<dim3((NH * QHD) / 128, SEQ / 128), 256>>>(qlat, q_b_w, qbuf, SEQ, NH * QHD, QLR);
    sgemm_nt<<<dim3((NH * (NOPE + VHD)) / 128, SEQ / 128), 256>>>(kvlat, kv_b_w, kvbuf,
                                                                  SEQ, NH * (NOPE + VHD), KVLR);
    rope_q_kernel<<<SEQ, 512>>>(qbuf);
    flash_kernel<<<dim3(SEQ / 64, NH), 256, FLASH_SMEM_BYTES>>>(qbuf, kvbuf, kpe, attnbuf);
    sgemm_nt<<<dim3(HDIM / 128, SEQ / 128), 256>>>(attnbuf, o_w, out, SEQ, HDIM, NH * VHD);
}

// round 10
// speedup vs baseline: 3.5402x; 1.4207x over previous
#include <cuda_runtime.h>
#include <cuda_bf16.h>
#include <math.h>
#include <stdint.h>

#define SEQ   2048
#define HDIM  2048
#define NH    16
#define QLR   1536
#define KVLR  512
#define NOPE  128
#define ROPEDIM 64
#define VHD   128
#define QHD   192   // NOPE + ROPE

// ---------------- scratch arena (no allocations allowed) ----------------
#define OFF_QLAT    0
#define OFF_KVLATPE (OFF_QLAT    + SEQ*QLR)
#define OFF_KVLAT   (OFF_KVLATPE + SEQ*(KVLR+ROPEDIM))
#define OFF_KPE     (OFF_KVLAT   + SEQ*KVLR)
#define OFF_Q       (OFF_KPE     + SEQ*ROPEDIM)
#define OFF_KV      (OFF_Q       + SEQ*NH*QHD)
#define OFF_ATTN    (OFF_KV      + SEQ*NH*(NOPE+VHD))
#define SCRATCH_TOTAL (OFF_ATTN  + SEQ*NH*VHD)

__device__ float g_scratch[SCRATCH_TOTAL];

// ---------------- tf32 helpers ----------------
__device__ __forceinline__ uint32_t f2tf32(float x) {
    uint32_t r;
    asm("cvt.rna.tf32.f32 %0, %1;" : "=r"(r) : "f"(x));
    return r;
}

__device__ __forceinline__ void mma_tf32(float4& d,
                                         uint32_t a0, uint32_t a1, uint32_t a2, uint32_t a3,
                                         uint32_t b0, uint32_t b1) {
    asm volatile(
        "mma.sync.aligned.m16n8k8.row.col.f32.tf32.tf32.f32 "
        "{%0,%1,%2,%3}, {%4,%5,%6,%7}, {%8,%9}, {%0,%1,%2,%3};"
        : "+f"(d.x), "+f"(d.y), "+f"(d.z), "+f"(d.w)
        : "r"(a0), "r"(a1), "r"(a2), "r"(a3), "r"(b0), "r"(b1));
}

// ---------------- tf32 tensor-core NT GEMM: C[M,N] = A[M,K] @ B[N,K]^T --------
// 128x128 tile, BK=8, 256 threads (8 warps, 2x4), warp tile 64x32 (4x4 atoms).
// smem [k][m] / [k][n], stride 136 words -> conflict-free fragment loads.
#define TS 136
__global__ __launch_bounds__(256) void sgemm_tf32(const float* __restrict__ A,
                                                  const float* __restrict__ B,
                                                  float* __restrict__ C,
                                                  int M, int N, int K) {
    __shared__ uint32_t As[8 * TS];
    __shared__ uint32_t Bs[8 * TS];

    const int tid  = threadIdx.x;
    const int lane = tid & 31;
    const int wid  = tid >> 5;
    const int warp_m = (wid & 1) * 64;     // 2 warps along M
    const int warp_n = (wid >> 1) * 32;    // 4 warps along N
    const int row0 = blockIdx.y * 128;
    const int col0 = blockIdx.x * 128;

    const int kr = lane & 3;               // k within fragment
    const int mr = lane >> 2;              // row/col group within fragment

    float4 acc[4][4];
#pragma unroll
    for (int i = 0; i < 4; i++)
#pragma unroll
        for (int j = 0; j < 4; j++) acc[i][j] = make_float4(0.f, 0.f, 0.f, 0.f);

    // staging: pair of threads per row, float4 each
    const int lr = tid >> 1;               // 0..127
    const int lk = (tid & 1) * 4;          // 0 or 4
    const bool aval = (row0 + lr) < M;
    const bool bval = (col0 + lr) < N;
    const float* Aptr = A + (size_t)(row0 + lr) * K + lk;
    const float* Bptr = B + (size_t)(col0 + lr) * K + lk;

    for (int k0 = 0; k0 < K; k0 += 8) {
        float4 av = aval ? *(const float4*)(Aptr + k0) : make_float4(0.f, 0.f, 0.f, 0.f);
        float4 bv = bval ? *(const float4*)(Bptr + k0) : make_float4(0.f, 0.f, 0.f, 0.f);
        As[(lk + 0) * TS + lr] = f2tf32(av.x);
        As[(lk + 1) * TS + lr] = f2tf32(av.y);
        As[(lk + 2) * TS + lr] = f2tf32(av.z);
        As[(lk + 3) * TS + lr] = f2tf32(av.w);
        Bs[(lk + 0) * TS + lr] = f2tf32(bv.x);
        Bs[(lk + 1) * TS + lr] = f2tf32(bv.y);
        Bs[(lk + 2) * TS + lr] = f2tf32(bv.z);
        Bs[(lk + 3) * TS + lr] = f2tf32(bv.w);
        __syncthreads();

        uint32_t a[4][4];
#pragma unroll
        for (int ma = 0; ma < 4; ma++) {
            const int base = warp_m + ma * 16 + mr;
            a[ma][0] = As[kr * TS + base];
            a[ma][1] = As[kr * TS + base + 8];
            a[ma][2] = As[(kr + 4) * TS + base];
            a[ma][3] = As[(kr + 4) * TS + base + 8];
        }
        uint32_t b[4][2];
#pragma unroll
        for (int nb = 0; nb < 4; nb++) {
            const int nbase = warp_n + nb * 8 + mr;
            b[nb][0] = Bs[kr * TS + nbase];
            b[nb][1] = Bs[(kr + 4) * TS + nbase];
        }
#pragma unroll
        for (int ma = 0; ma < 4; ma++)
#pragma unroll
            for (int nb = 0; nb < 4; nb++)
                mma_tf32(acc[ma][nb], a[ma][0], a[ma][1], a[ma][2], a[ma][3],
                         b[nb][0], b[nb][1]);
        __syncthreads();
    }

    // epilogue: c0 (r, c), c1 (r, c+1), c2 (r+8, c), c3 (r+8, c+1)
#pragma unroll
    for (int ma = 0; ma < 4; ma++) {
        const int r = row0 + warp_m + ma * 16 + (lane >> 2);
        if (r >= M) continue;
#pragma unroll
        for (int nb = 0; nb < 4; nb++) {
            const int c = col0 + warp_n + nb * 8 + 2 * (lane & 3);
            if (c < N) {
                float* p0 = C + (size_t)r * N + c;
                p0[0] = acc[ma][nb].x;
                p0[1] = acc[ma][nb].y;
                float* p1 = p0 + (size_t)8 * N;
                p1[0] = acc[ma][nb].z;
                p1[1] = acc[ma][nb].w;
            }
        }
    }
}

// ---------------- RMS norms ----------------
__global__ __launch_bounds__(256) void rms_q_kernel(float* __restrict__ x,
                                                    const float* __restrict__ w) {
    __shared__ float sbuf[256];
    const int row = blockIdx.x;
    float* p = x + (size_t)row * QLR;
    float ss = 0.0f;
    for (int d = threadIdx.x; d < QLR; d += 256) { float v = p[d]; ss += v * v; }
    sbuf[threadIdx.x] = ss;
    __syncthreads();
    if (threadIdx.x == 0) {
        float r = 0.0f;
        for (int i = 0; i < 256; i++) r += sbuf[i];
        sbuf[0] = r;
    }
    __syncthreads();
    const float inv = rsqrtf(sbuf[0] * (1.0f / QLR) + 1e-6f);
    for (int d = threadIdx.x; d < QLR; d += 256) p[d] = p[d] * inv * w[d];
}

__global__ __launch_bounds__(256) void rms_kv_kernel(const float* __restrict__ xin,
                                                     const float* __restrict__ w,
                                                     float* __restrict__ xout) {
    __shared__ float sbuf[256];
    const int row = blockIdx.x;
    const float* p = xin + (size_t)row * (KVLR + ROPEDIM);
    float ss = 0.0f;
    for (int d = threadIdx.x; d < KVLR; d += 256) { float v = p[d]; ss += v * v; }
    sbuf[threadIdx.x] = ss;
    __syncthreads();
    if (threadIdx.x == 0) {
        float r = 0.0f;
        for (int i = 0; i < 256; i++) r += sbuf[i];
        sbuf[0] = r;
    }
    __syncthreads();
    const float inv = rsqrtf(sbuf[0] * (1.0f / KVLR) + 1e-6f);
    float* o = xout + (size_t)row * KVLR;
    for (int d = threadIdx.x; d < KVLR; d += 256) o[d] = p[d] * inv * w[d];
}

// ---------------- RoPE: half-split pairing, NEGATED rotation sign (validated R8)
__device__ __forceinline__ float rope_invfreq(int j) {
    return exp2f(-(float)j * (13.287712379549449f / 32.0f));  // 10000^(-j/32)
}

__global__ void rope_q_kernel(float* __restrict__ q) {
    const int t = blockIdx.x;
    const int h = threadIdx.x >> 5;     // 0..15
    const int j = threadIdx.x & 31;     // pair index 0..31
    float* base = q + (size_t)t * (NH * QHD) + h * QHD + NOPE;
    float c, s;
    sincosf((float)t * rope_invfreq(j), &c, &s);
    const float x0 = base[j];
    const float x1 = base[j + 32];
    base[j]      = x0 * c + x1 * s;
    base[j + 32] = x1 * c - x0 * s;
}

__global__ void rope_k_kernel(const float* __restrict__ kvlatpe, float* __restrict__ kpe) {
    const int t = blockIdx.x;
    const int j = threadIdx.x;   // 0..31
    const float* base = kvlatpe + (size_t)t * (KVLR + ROPEDIM) + KVLR;
    float c, s;
    sincosf((float)t * rope_invfreq(j), &c, &s);
    const float x0 = base[j];
    const float x1 = base[j + 32];
    kpe[(size_t)t * ROPEDIM + j]      = x0 * c + x1 * s;
    kpe[(size_t)t * ROPEDIM + j + 32] = x1 * c - x0 * s;
}

// ---------------- Flash attention (fp32, causal, smem softmax) ----------------
#define FLASH_SMEM_FLOATS (192 * 65 * 2 + 64 * 128 + 64 * 65 + 3 * 64)
#define FLASH_SMEM_BYTES  (FLASH_SMEM_FLOATS * 4)

__global__ __launch_bounds__(256) void flash_kernel(const float* __restrict__ q,
                                                    const float* __restrict__ kv,
                                                    const float* __restrict__ kpe,
                                                    float* __restrict__ attn) {
    extern __shared__ __align__(16) float sm[];
    float* Qs  = sm;                   // [192][65] d-major
    float* Ks  = sm + 192 * 65;        // [192][65] d-major
    float* Vs  = Ks + 192 * 65;        // [64][128]
    float* Ps  = Vs + 64 * 128;        // [64][65]
    float* m_s = Ps + 64 * 65;         // [64]
    float* l_s = m_s + 64;             // [64]
    float* c_s = l_s + 64;             // [64]

    const int tid = threadIdx.x;
    const int tx = tid & 15;
    const int ty = tid >> 4;
    const int qb = blockIdx.x;
    const int h  = blockIdx.y;
    const int qbase = qb * 64;
    const float scale = 0.07216878364870323f;  // 192^-0.5

    for (int idx = tid; idx < 64 * 192; idx += 256) {
        int r = idx / 192, d = idx - r * 192;
        Qs[d * 65 + r] = q[(size_t)(qbase + r) * (NH * QHD) + h * QHD + d] * scale;
    }
    if (tid < 64) { m_s[tid] = -1e30f; l_s[tid] = 0.0f; }

    float acc[4][8];
#pragma unroll
    for (int i = 0; i < 4; i++)
#pragma unroll
        for (int j = 0; j < 8; j++) acc[i][j] = 0.0f;

    for (int kb = 0; kb <= qb; kb++) {
        const int kbase = kb * 64;
        __syncthreads();
        for (int idx = tid; idx < 64 * 192; idx += 256) {
            int c = idx / 192, d = idx - c * 192;
            float v = (d < NOPE)
                ? kv[(size_t)(kbase + c) * (NH * (NOPE + VHD)) + h * (NOPE + VHD) + d]
                : kpe[(size_t)(kbase + c) * ROPEDIM + (d - NOPE)];
            Ks[d * 65 + c] = v;
        }
        for (int idx = tid; idx < 64 * 128; idx += 256) {
            int c = idx >> 7, d = idx & 127;
            Vs[c * 128 + d] =
                kv[(size_t)(kbase + c) * (NH * (NOPE + VHD)) + h * (NOPE + VHD) + NOPE + d];
        }
        __syncthreads();

        float s[4][4];
#pragma unroll
        for (int i = 0; i < 4; i++)
#pragma unroll
            for (int j = 0; j < 4; j++) s[i][j] = 0.0f;

#pragma unroll 4
        for (int d = 0; d < 192; d++) {
            float a0 = Qs[d * 65 + ty * 4 + 0];
            float a1 = Qs[d * 65 + ty * 4 + 1];
            float a2 = Qs[d * 65 + ty * 4 + 2];
            float a3 = Qs[d * 65 + ty * 4 + 3];
            float b0 = Ks[d * 65 + tx * 4 + 0];
            float b1 = Ks[d * 65 + tx * 4 + 1];
            float b2 = Ks[d * 65 + tx * 4 + 2];
            float b3 = Ks[d * 65 + tx * 4 + 3];
            s[0][0] += a0 * b0; s[0][1] += a0 * b1; s[0][2] += a0 * b2; s[0][3] += a0 * b3;
            s[1][0] += a1 * b0; s[1][1] += a1 * b1; s[1][2] += a1 * b2; s[1][3] += a1 * b3;
            s[2][0] += a2 * b0; s[2][1] += a2 * b1; s[2][2] += a2 * b2; s[2][3] += a2 * b3;
            s[3][0] += a3 * b0; s[3][1] += a3 * b1; s[3][2] += a3 * b2; s[3][3] += a3 * b3;
        }

        if (kb == qb) {
#pragma unroll
            for (int i = 0; i < 4; i++)
#pragma unroll
                for (int j = 0; j < 4; j++)
                    if (tx * 4 + j > ty * 4 + i) s[i][j] = -1e30f;
        }

#pragma unroll
        for (int i = 0; i < 4; i++)
#pragma unroll
            for (int j = 0; j < 4; j++)
                Ps[(ty * 4 + i) * 65 + tx * 4 + j] = s[i][j];
        __syncthreads();

        if (tid < 64) {
            const int row = tid;
            float mx = -1e30f;
            for (int c = 0; c < 64; c++) mx = fmaxf(mx, Ps[row * 65 + c]);
            float mold = m_s[row];
            float mnew = fmaxf(mold, mx);
            float corr = __expf(mold - mnew);
            float rs = 0.0f;
            for (int c = 0; c < 64; c++) {
                float e = __expf(Ps[row * 65 + c] - mnew);
                Ps[row * 65 + c] = e;
                rs += e;
            }
            l_s[row] = l_s[row] * corr + rs;
            m_s[row] = mnew;
            c_s[row] = corr;
        }
        __syncthreads();

#pragma unroll
        for (int i = 0; i < 4; i++) {
            float corr = c_s[ty * 4 + i];
#pragma unroll
            for (int j = 0; j < 8; j++) acc[i][j] *= corr;
        }
#pragma unroll 2
        for (int kk = 0; kk < 64; kk++) {
            const float4 v0 = *(const float4*)&Vs[kk * 128 + tx * 8];
            const float4 v1 = *(const float4*)&Vs[kk * 128 + tx * 8 + 4];
#pragma unroll
            for (int i = 0; i < 4; i++) {
                float p = Ps[(ty * 4 + i) * 65 + kk];
                acc[i][0] += p * v0.x; acc[i][1] += p * v0.y;
                acc[i][2] += p * v0.z; acc[i][3] += p * v0.w;
                acc[i][4] += p * v1.x; acc[i][5] += p * v1.y;
                acc[i][6] += p * v1.z; acc[i][7] += p * v1.w;
            }
        }
    }

#pragma unroll
    for (int i = 0; i < 4; i++) {
        float inv = 1.0f / l_s[ty * 4 + i];
        int t = qbase + ty * 4 + i;
        float* o = attn + (size_t)t * (NH * VHD) + h * VHD + tx * 8;
#pragma unroll
        for (int j = 0; j < 8; j++) o[j] = acc[i][j] * inv;
    }
}

// ---------------- launch ----------------
extern "C" void kernel_launch(void* const* d_in, const int* in_sizes, int n_in,
                              void* d_out, int out_size) {
    const float *hidden = nullptr, *q_a_w = nullptr, *q_a_ln_w = nullptr, *q_b_w = nullptr,
                *kv_a_w = nullptr, *kv_a_ln_w = nullptr, *kv_b_w = nullptr, *o_w = nullptr;
    for (int i = 0; i < n_in; i++) {
        const float* p = (const float*)d_in[i];
        switch (in_sizes[i]) {
            case QLR * HDIM:                q_a_w = p;    break;  // 3145728
            case QLR:                       q_a_ln_w = p; break;  // 1536
            case NH * QHD * QLR:            q_b_w = p;    break;  // 4718592
            case (KVLR + ROPEDIM) * HDIM:   kv_a_w = p;   break;  // 1179648
            case KVLR:                      kv_a_ln_w = p;break;  // 512
            case NH * (NOPE + VHD) * KVLR:  kv_b_w = p;   break;  // 2097152
            case SEQ * HDIM:  if (!hidden) hidden = p; else o_w = p; break; // 4194304 x2
        }
    }
    float* out = (float*)d_out;

    float* base = nullptr;
    cudaGetSymbolAddress((void**)&base, g_scratch);
    float* qlat    = base + OFF_QLAT;
    float* kvlatpe = base + OFF_KVLATPE;
    float* kvlat   = base + OFF_KVLAT;
    float* kpe     = base + OFF_KPE;
    float* qbuf    = base + OFF_Q;
    float* kvbuf   = base + OFF_KV;
    float* attnbuf = base + OFF_ATTN;

    cudaFuncSetAttribute(flash_kernel, cudaFuncAttributeMaxDynamicSharedMemorySize,
                         FLASH_SMEM_BYTES);

    sgemm_tf32<<<dim3(QLR / 128, SEQ / 128), 256>>>(hidden, q_a_w, qlat, SEQ, QLR, HDIM);
    sgemm_tf32<<<dim3((KVLR + ROPEDIM + 127) / 128, SEQ / 128), 256>>>(hidden, kv_a_w, kvlatpe,
                                                                       SEQ, KVLR + ROPEDIM, HDIM);
    rms_q_kernel<<<SEQ, 256>>>(qlat, q_a_ln_w);
    rms_kv_kernel<<<SEQ, 256>>>(kvlatpe, kv_a_ln_w, kvlat);
    rope_k_kernel<<<SEQ, 32>>>(kvlatpe, kpe);
    sgemm_tf32<<<dim3((NH * QHD) / 128, SEQ / 128), 256>>>(qlat, q_b_w, qbuf, SEQ, NH * QHD, QLR);
    sgemm_tf32<<<dim3((NH * (NOPE + VHD)) / 128, SEQ / 128), 256>>>(kvlat, kv_b_w, kvbuf,
                                                                    SEQ, NH * (NOPE + VHD), KVLR);
    rope_q_kernel<<<SEQ, 512>>>(qbuf);
    flash_kernel<<<dim3(SEQ / 64, NH), 256, FLASH_SMEM_BYTES>>>(qbuf, kvbuf, kpe, attnbuf);
    sgemm_tf32<<<dim3(HDIM / 128, SEQ / 128), 256>>>(attnbuf, o_w, out, SEQ, HDIM, NH * VHD);
}

// round 13
// speedup vs baseline: 4.6489x; 1.3132x over previous
#include <cuda_runtime.h>
#include <cuda_bf16.h>
#include <math.h>
#include <stdint.h>

#define SEQ   2048
#define HDIM  2048
#define NH    16
#define QLR   1536
#define KVLR  512
#define NOPE  128
#define ROPEDIM 64
#define VHD   128
#define QHD   192   // NOPE + ROPE

// ---------------- scratch arena (no allocations allowed) ----------------
#define OFF_QLAT    0
#define OFF_KVLATPE (OFF_QLAT    + SEQ*QLR)
#define OFF_KVLAT   (OFF_KVLATPE + SEQ*(KVLR+ROPEDIM))
#define OFF_KPE     (OFF_KVLAT   + SEQ*KVLR)
#define OFF_Q       (OFF_KPE     + SEQ*ROPEDIM)
#define OFF_KV      (OFF_Q       + SEQ*NH*QHD)
#define OFF_ATTN    (OFF_KV      + SEQ*NH*(NOPE+VHD))
#define SCRATCH_TOTAL (OFF_ATTN  + SEQ*NH*VHD)

__device__ float g_scratch[SCRATCH_TOTAL];

// ---------------- tf32 helpers ----------------
__device__ __forceinline__ uint32_t f2tf32(float x) {
    uint32_t r;
    asm("cvt.rna.tf32.f32 %0, %1;" : "=r"(r) : "f"(x));
    return r;
}

__device__ __forceinline__ void split_tf32(float x, uint32_t& hi, uint32_t& lo) {
    hi = f2tf32(x);
    lo = f2tf32(x - __uint_as_float(hi));
}

__device__ __forceinline__ void mma_tf32(float4& d,
                                         uint32_t a0, uint32_t a1, uint32_t a2, uint32_t a3,
                                         uint32_t b0, uint32_t b1) {
    asm volatile(
        "mma.sync.aligned.m16n8k8.row.col.f32.tf32.tf32.f32 "
        "{%0,%1,%2,%3}, {%4,%5,%6,%7}, {%8,%9}, {%0,%1,%2,%3};"
        : "+f"(d.x), "+f"(d.y), "+f"(d.z), "+f"(d.w)
        : "r"(a0), "r"(a1), "r"(a2), "r"(a3), "r"(b0), "r"(b1));
}

// ---------------- tf32 tensor-core NT GEMM: C[M,N] = A[M,K] @ B[N,K]^T --------
// (validated round 10)
#define TS 136
__global__ __launch_bounds__(256) void sgemm_tf32(const float* __restrict__ A,
                                                  const float* __restrict__ B,
                                                  float* __restrict__ C,
                                                  int M, int N, int K) {
    __shared__ uint32_t As[8 * TS];
    __shared__ uint32_t Bs[8 * TS];

    const int tid  = threadIdx.x;
    const int lane = tid & 31;
    const int wid  = tid >> 5;
    const int warp_m = (wid & 1) * 64;
    const int warp_n = (wid >> 1) * 32;
    const int row0 = blockIdx.y * 128;
    const int col0 = blockIdx.x * 128;

    const int kr = lane & 3;
    const int mr = lane >> 2;

    float4 acc[4][4];
#pragma unroll
    for (int i = 0; i < 4; i++)
#pragma unroll
        for (int j = 0; j < 4; j++) acc[i][j] = make_float4(0.f, 0.f, 0.f, 0.f);

    const int lr = tid >> 1;
    const int lk = (tid & 1) * 4;
    const bool aval = (row0 + lr) < M;
    const bool bval = (col0 + lr) < N;
    const float* Aptr = A + (size_t)(row0 + lr) * K + lk;
    const float* Bptr = B + (size_t)(col0 + lr) * K + lk;

    for (int k0 = 0; k0 < K; k0 += 8) {
        float4 av = aval ? *(const float4*)(Aptr + k0) : make_float4(0.f, 0.f, 0.f, 0.f);
        float4 bv = bval ? *(const float4*)(Bptr + k0) : make_float4(0.f, 0.f, 0.f, 0.f);
        As[(lk + 0) * TS + lr] = f2tf32(av.x);
        As[(lk + 1) * TS + lr] = f2tf32(av.y);
        As[(lk + 2) * TS + lr] = f2tf32(av.z);
        As[(lk + 3) * TS + lr] = f2tf32(av.w);
        Bs[(lk + 0) * TS + lr] = f2tf32(bv.x);
        Bs[(lk + 1) * TS + lr] = f2tf32(bv.y);
        Bs[(lk + 2) * TS + lr] = f2tf32(bv.z);
        Bs[(lk + 3) * TS + lr] = f2tf32(bv.w);
        __syncthreads();

        uint32_t a[4][4];
#pragma unroll
        for (int ma = 0; ma < 4; ma++) {
            const int base = warp_m + ma * 16 + mr;
            a[ma][0] = As[kr * TS + base];
            a[ma][1] = As[kr * TS + base + 8];
            a[ma][2] = As[(kr + 4) * TS + base];
            a[ma][3] = As[(kr + 4) * TS + base + 8];
        }
        uint32_t b[4][2];
#pragma unroll
        for (int nb = 0; nb < 4; nb++) {
            const int nbase = warp_n + nb * 8 + mr;
            b[nb][0] = Bs[kr * TS + nbase];
            b[nb][1] = Bs[(kr + 4) * TS + nbase];
        }
#pragma unroll
        for (int ma = 0; ma < 4; ma++)
#pragma unroll
            for (int nb = 0; nb < 4; nb++)
                mma_tf32(acc[ma][nb], a[ma][0], a[ma][1], a[ma][2], a[ma][3],
                         b[nb][0], b[nb][1]);
        __syncthreads();
    }

#pragma unroll
    for (int ma = 0; ma < 4; ma++) {
        const int r = row0 + warp_m + ma * 16 + (lane >> 2);
        if (r >= M) continue;
#pragma unroll
        for (int nb = 0; nb < 4; nb++) {
            const int c = col0 + warp_n + nb * 8 + 2 * (lane & 3);
            if (c < N) {
                float* p0 = C + (size_t)r * N + c;
                p0[0] = acc[ma][nb].x;
                p0[1] = acc[ma][nb].y;
                float* p1 = p0 + (size_t)8 * N;
                p1[0] = acc[ma][nb].z;
                p1[1] = acc[ma][nb].w;
            }
        }
    }
}

// ---------------- RMS norms ----------------
__global__ __launch_bounds__(256) void rms_q_kernel(float* __restrict__ x,
                                                    const float* __restrict__ w) {
    __shared__ float sbuf[256];
    const int row = blockIdx.x;
    float* p = x + (size_t)row * QLR;
    float ss = 0.0f;
    for (int d = threadIdx.x; d < QLR; d += 256) { float v = p[d]; ss += v * v; }
    sbuf[threadIdx.x] = ss;
    __syncthreads();
    if (threadIdx.x == 0) {
        float r = 0.0f;
        for (int i = 0; i < 256; i++) r += sbuf[i];
        sbuf[0] = r;
    }
    __syncthreads();
    const float inv = rsqrtf(sbuf[0] * (1.0f / QLR) + 1e-6f);
    for (int d = threadIdx.x; d < QLR; d += 256) p[d] = p[d] * inv * w[d];
}

__global__ __launch_bounds__(256) void rms_kv_kernel(const float* __restrict__ xin,
                                                     const float* __restrict__ w,
                                                     float* __restrict__ xout) {
    __shared__ float sbuf[256];
    const int row = blockIdx.x;
    const float* p = xin + (size_t)row * (KVLR + ROPEDIM);
    float ss = 0.0f;
    for (int d = threadIdx.x; d < KVLR; d += 256) { float v = p[d]; ss += v * v; }
    sbuf[threadIdx.x] = ss;
    __syncthreads();
    if (threadIdx.x == 0) {
        float r = 0.0f;
        for (int i = 0; i < 256; i++) r += sbuf[i];
        sbuf[0] = r;
    }
    __syncthreads();
    const float inv = rsqrtf(sbuf[0] * (1.0f / KVLR) + 1e-6f);
    float* o = xout + (size_t)row * KVLR;
    for (int d = threadIdx.x; d < KVLR; d += 256) o[d] = p[d] * inv * w[d];
}

// ---------------- RoPE: half-split pairing, NEGATED rotation sign (validated R8)
__device__ __forceinline__ float rope_invfreq(int j) {
    return exp2f(-(float)j * (13.287712379549449f / 32.0f));
}

__global__ void rope_q_kernel(float* __restrict__ q) {
    const int t = blockIdx.x;
    const int h = threadIdx.x >> 5;
    const int j = threadIdx.x & 31;
    float* base = q + (size_t)t * (NH * QHD) + h * QHD + NOPE;
    float c, s;
    sincosf((float)t * rope_invfreq(j), &c, &s);
    const float x0 = base[j];
    const float x1 = base[j + 32];
    base[j]      = x0 * c + x1 * s;
    base[j + 32] = x1 * c - x0 * s;
}

__global__ void rope_k_kernel(const float* __restrict__ kvlatpe, float* __restrict__ kpe) {
    const int t = blockIdx.x;
    const int j = threadIdx.x;
    const float* base = kvlatpe + (size_t)t * (KVLR + ROPEDIM) + KVLR;
    float c, s;
    sincosf((float)t * rope_invfreq(j), &c, &s);
    const float x0 = base[j];
    const float x1 = base[j + 32];
    kpe[(size_t)t * ROPEDIM + j]      = x0 * c + x1 * s;
    kpe[(size_t)t * ROPEDIM + j + 32] = x1 * c - x0 * s;
}

// ---------------- Flash attention: tensor-core S (tf32x2) + PV (tf32) ---------
// 64x64 tiles, 256 threads = 8 warps.
// Qs/Ks: [row][d] fp32, stride 200 (=8 mod 32 -> conflict-free frag loads)
// Vs:    [k][n] tf32, stride 136 (=8 mod 32)
// Ps:    [m][k] fp32, stride 68  (=4 mod 32)
#define FQ 200
#define FV 136
#define FP 68
#define F_QS 0
#define F_KS (F_QS + 64 * FQ)            // 12800
#define F_VS (F_KS + 64 * FQ)            // 25600
#define F_PS (F_VS + 64 * FV)            // 34304
#define F_MS (F_PS + 64 * FP)            // 38656
#define F_LS (F_MS + 64)
#define F_CS (F_LS + 64)
#define FLASH_SMEM_WORDS (F_CS + 64)     // 38848
#define FLASH_SMEM_BYTES (FLASH_SMEM_WORDS * 4)

__global__ __launch_bounds__(256) void flash_kernel(const float* __restrict__ q,
                                                    const float* __restrict__ kv,
                                                    const float* __restrict__ kpe,
                                                    float* __restrict__ attn) {
    extern __shared__ __align__(16) float sm[];
    float*    Qs  = sm + F_QS;
    float*    Ks  = sm + F_KS;
    uint32_t* Vs  = (uint32_t*)(sm + F_VS);
    float*    Ps  = sm + F_PS;
    float*    m_s = sm + F_MS;
    float*    l_s = sm + F_LS;
    float*    c_s = sm + F_CS;

    const int tid  = threadIdx.x;
    const int lane = tid & 31;
    const int wid  = tid >> 5;
    const int kr = lane & 3;
    const int mr = lane >> 2;
    const int qb = blockIdx.x;
    const int h  = blockIdx.y;
    const int qbase = qb * 64;
    const float scale = 0.07216878364870323f;  // 192^-0.5

    // S warp grid: 2 (M) x 4 (N); warp tile 32x16
    const int s_wm = (wid & 1) * 32;
    const int s_wn = (wid >> 1) * 16;
    // PV warp grid: 2 (M) x 4 (N); warp tile 32x32
    const int p_wm = (wid & 1) * 32;
    const int p_wn = (wid >> 1) * 32;

    // stage Q once: [r][d], gmem-coalesced, conflict-free STS
    for (int idx = tid; idx < 64 * 192; idx += 256) {
        int r = idx / 192, d = idx - r * 192;
        Qs[r * FQ + d] = q[(size_t)(qbase + r) * (NH * QHD) + h * QHD + d] * scale;
    }
    if (tid < 64) { m_s[tid] = -1e30f; l_s[tid] = 0.0f; }

    float4 acc[2][4];
#pragma unroll
    for (int i = 0; i < 2; i++)
#pragma unroll
        for (int j = 0; j < 4; j++) acc[i][j] = make_float4(0.f, 0.f, 0.f, 0.f);

    for (int kb = 0; kb <= qb; kb++) {
        const int kbase = kb * 64;
        __syncthreads();   // prev iteration's PV finished reading Ps/Vs; Qs staged
        for (int idx = tid; idx < 64 * 192; idx += 256) {
            int c = idx / 192, d = idx - c * 192;
            float v = (d < NOPE)
                ? kv[(size_t)(kbase + c) * (NH * (NOPE + VHD)) + h * (NOPE + VHD) + d]
                : kpe[(size_t)(kbase + c) * ROPEDIM + (d - NOPE)];
            Ks[c * FQ + d] = v;
        }
        for (int idx = tid; idx < 64 * 128; idx += 256) {
            int c = idx >> 7, d = idx & 127;
            Vs[c * FV + d] = f2tf32(
                kv[(size_t)(kbase + c) * (NH * (NOPE + VHD)) + h * (NOPE + VHD) + NOPE + d]);
        }
        __syncthreads();

        // ---- S = Q K^T via tf32x2 (hi/lo split), fp32 accumulate ----
        float4 sc[2][2];
#pragma unroll
        for (int i = 0; i < 2; i++)
#pragma unroll
            for (int j = 0; j < 2; j++) sc[i][j] = make_float4(0.f, 0.f, 0.f, 0.f);

        for (int k0 = 0; k0 < 192; k0 += 8) {
            uint32_t ah[2][4], al[2][4];
#pragma unroll
            for (int ma = 0; ma < 2; ma++) {
                const int r0 = s_wm + ma * 16 + mr;
                split_tf32(Qs[r0 * FQ + k0 + kr],            ah[ma][0], al[ma][0]);
                split_tf32(Qs[(r0 + 8) * FQ + k0 + kr],      ah[ma][1], al[ma][1]);
                split_tf32(Qs[r0 * FQ + k0 + kr + 4],        ah[ma][2], al[ma][2]);
                split_tf32(Qs[(r0 + 8) * FQ + k0 + kr + 4],  ah[ma][3], al[ma][3]);
            }
            uint32_t bh[2][2], bl[2][2];
#pragma unroll
            for (int nb = 0; nb < 2; nb++) {
                const int n0 = s_wn + nb * 8 + mr;
                split_tf32(Ks[n0 * FQ + k0 + kr],     bh[nb][0], bl[nb][0]);
                split_tf32(Ks[n0 * FQ + k0 + kr + 4], bh[nb][1], bl[nb][1]);
            }
#pragma unroll
            for (int ma = 0; ma < 2; ma++)
#pragma unroll
                for (int nb = 0; nb < 2; nb++) {
                    mma_tf32(sc[ma][nb], ah[ma][0], ah[ma][1], ah[ma][2], ah[ma][3],
                             bh[nb][0], bh[nb][1]);
                    mma_tf32(sc[ma][nb], al[ma][0], al[ma][1], al[ma][2], al[ma][3],
                             bh[nb][0], bh[nb][1]);
                    mma_tf32(sc[ma][nb], ah[ma][0], ah[ma][1], ah[ma][2], ah[ma][3],
                             bl[nb][0], bl[nb][1]);
                }
        }

        // mask diagonal tile + write scores to Ps
#pragma unroll
        for (int ma = 0; ma < 2; ma++) {
            const int r0 = s_wm + ma * 16 + (lane >> 2);
#pragma unroll
            for (int nb = 0; nb < 2; nb++) {
                const int c0 = s_wn + nb * 8 + 2 * (lane & 3);
                float4 v = sc[ma][nb];
                if (kb == qb) {
                    if (c0 > r0)         v.x = -1e30f;
                    if (c0 + 1 > r0)     v.y = -1e30f;
                    if (c0 > r0 + 8)     v.z = -1e30f;
                    if (c0 + 1 > r0 + 8) v.w = -1e30f;
                }
                Ps[r0 * FP + c0]           = v.x;
                Ps[r0 * FP + c0 + 1]       = v.y;
                Ps[(r0 + 8) * FP + c0]     = v.z;
                Ps[(r0 + 8) * FP + c0 + 1] = v.w;
            }
        }
        __syncthreads();

        // ---- per-row online softmax (serial row scan) ----
        if (tid < 64) {
            const int row = tid;
            float mx = -1e30f;
            for (int c = 0; c < 64; c++) mx = fmaxf(mx, Ps[row * FP + c]);
            float mold = m_s[row];
            float mnew = fmaxf(mold, mx);
            float corr = __expf(mold - mnew);
            float rs = 0.0f;
            for (int c = 0; c < 64; c++) {
                float e = __expf(Ps[row * FP + c] - mnew);
                Ps[row * FP + c] = e;
                rs += e;
            }
            l_s[row] = l_s[row] * corr + rs;
            m_s[row] = mnew;
            c_s[row] = corr;
        }
        __syncthreads();

        // ---- acc = acc*corr + P @ V (single-pass tf32) ----
#pragma unroll
        for (int ma = 0; ma < 2; ma++) {
            const int r0 = p_wm + ma * 16 + (lane >> 2);
            const float c1 = c_s[r0];
            const float c2 = c_s[r0 + 8];
#pragma unroll
            for (int nb = 0; nb < 4; nb++) {
                acc[ma][nb].x *= c1; acc[ma][nb].y *= c1;
                acc[ma][nb].z *= c2; acc[ma][nb].w *= c2;
            }
        }
        for (int k0 = 0; k0 < 64; k0 += 8) {
            uint32_t a[2][4];
#pragma unroll
            for (int ma = 0; ma < 2; ma++) {
                const int r0 = p_wm + ma * 16 + mr;
                a[ma][0] = f2tf32(Ps[r0 * FP + k0 + kr]);
                a[ma][1] = f2tf32(Ps[(r0 + 8) * FP + k0 + kr]);
                a[ma][2] = f2tf32(Ps[r0 * FP + k0 + kr + 4]);
                a[ma][3] = f2tf32(Ps[(r0 + 8) * FP + k0 + kr + 4]);
            }
            uint32_t b[4][2];
#pragma unroll
            for (int nb = 0; nb < 4; nb++) {
                const int n0 = p_wn + nb * 8 + mr;
                b[nb][0] = Vs[(k0 + kr) * FV + n0];
                b[nb][1] = Vs[(k0 + kr + 4) * FV + n0];
            }
#pragma unroll
            for (int ma = 0; ma < 2; ma++)
#pragma unroll
                for (int nb = 0; nb < 4; nb++)
                    mma_tf32(acc[ma][nb], a[ma][0], a[ma][1], a[ma][2], a[ma][3],
                             b[nb][0], b[nb][1]);
        }
    }

    // epilogue: normalize by l and store
#pragma unroll
    for (int ma = 0; ma < 2; ma++) {
        const int r0 = p_wm + ma * 16 + (lane >> 2);
        const float inv1 = 1.0f / l_s[r0];
        const float inv2 = 1.0f / l_s[r0 + 8];
        const int t1 = qbase + r0;
        const int t2 = t1 + 8;
#pragma unroll
        for (int nb = 0; nb < 4; nb++) {
            const int c0 = p_wn + nb * 8 + 2 * (lane & 3);
            float* o1 = attn + (size_t)t1 * (NH * VHD) + h * VHD + c0;
            o1[0] = acc[ma][nb].x * inv1;
            o1[1] = acc[ma][nb].y * inv1;
            float* o2 = attn + (size_t)t2 * (NH * VHD) + h * VHD + c0;
            o2[0] = acc[ma][nb].z * inv2;
            o2[1] = acc[ma][nb].w * inv2;
        }
    }
}

// ---------------- launch ----------------
extern "C" void kernel_launch(void* const* d_in, const int* in_sizes, int n_in,
                              void* d_out, int out_size) {
    const float *hidden = nullptr, *q_a_w = nullptr, *q_a_ln_w = nullptr, *q_b_w = nullptr,
                *kv_a_w = nullptr, *kv_a_ln_w = nullptr, *kv_b_w = nullptr, *o_w = nullptr;
    for (int i = 0; i < n_in; i++) {
        const float* p = (const float*)d_in[i];
        switch (in_sizes[i]) {
            case QLR * HDIM:                q_a_w = p;    break;  // 3145728
            case QLR:                       q_a_ln_w = p; break;  // 1536
            case NH * QHD * QLR:            q_b_w = p;    break;  // 4718592
            case (KVLR + ROPEDIM) * HDIM:   kv_a_w = p;   break;  // 1179648
            case KVLR:                      kv_a_ln_w = p;break;  // 512
            case NH * (NOPE + VHD) * KVLR:  kv_b_w = p;   break;  // 2097152
            case SEQ * HDIM:  if (!hidden) hidden = p; else o_w = p; break; // 4194304 x2
        }
    }
    float* out = (float*)d_out;

    float* base = nullptr;
    cudaGetSymbolAddress((void**)&base, g_scratch);
    float* qlat    = base + OFF_QLAT;
    float* kvlatpe = base + OFF_KVLATPE;
    float* kvlat   = base + OFF_KVLAT;
    float* kpe     = base + OFF_KPE;
    float* qbuf    = base + OFF_Q;
    float* kvbuf   = base + OFF_KV;
    float* attnbuf = base + OFF_ATTN;

    cudaFuncSetAttribute(flash_kernel, cudaFuncAttributeMaxDynamicSharedMemorySize,
                         FLASH_SMEM_BYTES);

    sgemm_tf32<<<dim3(QLR / 128, SEQ / 128), 256>>>(hidden, q_a_w, qlat, SEQ, QLR, HDIM);
    sgemm_tf32<<<dim3((KVLR + ROPEDIM + 127) / 128, SEQ / 128), 256>>>(hidden, kv_a_w, kvlatpe,
                                                                       SEQ, KVLR + ROPEDIM, HDIM);
    rms_q_kernel<<<SEQ, 256>>>(qlat, q_a_ln_w);
    rms_kv_kernel<<<SEQ, 256>>>(kvlatpe, kv_a_ln_w, kvlat);
    rope_k_kernel<<<SEQ, 32>>>(kvlatpe, kpe);
    sgemm_tf32<<<dim3((NH * QHD) / 128, SEQ / 128), 256>>>(qlat, q_b_w, qbuf, SEQ, NH * QHD, QLR);
    sgemm_tf32<<<dim3((NH * (NOPE + VHD)) / 128, SEQ / 128), 256>>>(kvlat, kv_b_w, kvbuf,
                                                                    SEQ, NH * (NOPE + VHD), KVLR);
    rope_q_kernel<<<SEQ, 512>>>(qbuf);
    flash_kernel<<<dim3(SEQ / 64, NH), 256, FLASH_SMEM_BYTES>>>(qbuf, kvbuf, kpe, attnbuf);
    sgemm_tf32<<<dim3(HDIM / 128, SEQ / 128), 256>>>(attnbuf, o_w, out, SEQ, HDIM, NH * VHD);
}

// round 14
// speedup vs baseline: 4.9654x; 1.0681x over previous
#include <cuda_runtime.h>
#include <cuda_bf16.h>
#include <math.h>
#include <stdint.h>

#define SEQ   2048
#define HDIM  2048
#define NH    16
#define QLR   1536
#define KVLR  512
#define NOPE  128
#define ROPEDIM 64
#define VHD   128
#define QHD   192   // NOPE + ROPE

// ---------------- scratch arena (no allocations allowed) ----------------
#define OFF_QLAT    0
#define OFF_KVLATPE (OFF_QLAT    + SEQ*QLR)
#define OFF_KVLAT   (OFF_KVLATPE + SEQ*(KVLR+ROPEDIM))
#define OFF_KPE     (OFF_KVLAT   + SEQ*KVLR)
#define OFF_Q       (OFF_KPE     + SEQ*ROPEDIM)
#define OFF_KV      (OFF_Q       + SEQ*NH*QHD)
#define OFF_ATTN    (OFF_KV      + SEQ*NH*(NOPE+VHD))
#define SCRATCH_TOTAL (OFF_ATTN  + SEQ*NH*VHD)

__device__ float g_scratch[SCRATCH_TOTAL];

// ---------------- tf32 helpers ----------------
__device__ __forceinline__ uint32_t f2tf32(float x) {
    uint32_t r;
    asm("cvt.rna.tf32.f32 %0, %1;" : "=r"(r) : "f"(x));
    return r;
}

__device__ __forceinline__ void split_tf32(float x, uint32_t& hi, uint32_t& lo) {
    hi = f2tf32(x);
    lo = f2tf32(x - __uint_as_float(hi));
}

__device__ __forceinline__ void mma_tf32(float4& d,
                                         uint32_t a0, uint32_t a1, uint32_t a2, uint32_t a3,
                                         uint32_t b0, uint32_t b1) {
    asm volatile(
        "mma.sync.aligned.m16n8k8.row.col.f32.tf32.tf32.f32 "
        "{%0,%1,%2,%3}, {%4,%5,%6,%7}, {%8,%9}, {%0,%1,%2,%3};"
        : "+f"(d.x), "+f"(d.y), "+f"(d.z), "+f"(d.w)
        : "r"(a0), "r"(a1), "r"(a2), "r"(a3), "r"(b0), "r"(b1));
}

// ---------------- tf32 tensor-core NT GEMM: C[M,N] = A[M,K] @ B[N,K]^T --------
// 128x128 tile, BK=16, double-buffered smem, one sync/iter, 256 threads.
// Fragment/accumulator math identical to the round-10 validated kernel.
#define TS 136
#define BKG 16
__global__ __launch_bounds__(256) void sgemm_tf32(const float* __restrict__ A,
                                                  const float* __restrict__ B,
                                                  float* __restrict__ C,
                                                  int M, int N, int K) {
    __shared__ uint32_t As[2][BKG * TS];
    __shared__ uint32_t Bs[2][BKG * TS];

    const int tid  = threadIdx.x;
    const int lane = tid & 31;
    const int wid  = tid >> 5;
    const int warp_m = (wid & 1) * 64;
    const int warp_n = (wid >> 1) * 32;
    const int row0 = blockIdx.y * 128;
    const int col0 = blockIdx.x * 128;

    const int kr = lane & 3;
    const int mr = lane >> 2;

    float4 acc[4][4];
#pragma unroll
    for (int i = 0; i < 4; i++)
#pragma unroll
        for (int j = 0; j < 4; j++) acc[i][j] = make_float4(0.f, 0.f, 0.f, 0.f);

    const int lr = tid >> 1;           // 0..127
    const int lk = (tid & 1) * 8;      // 0 or 8
    const bool aval = (row0 + lr) < M;
    const bool bval = (col0 + lr) < N;
    const float* Aptr = A + (size_t)(row0 + lr) * K + lk;
    const float* Bptr = B + (size_t)(col0 + lr) * K + lk;
    const float4 z4 = make_float4(0.f, 0.f, 0.f, 0.f);

    // preload tile 0
    {
        float4 av0 = aval ? *(const float4*)(Aptr)     : z4;
        float4 av1 = aval ? *(const float4*)(Aptr + 4) : z4;
        float4 bv0 = bval ? *(const float4*)(Bptr)     : z4;
        float4 bv1 = bval ? *(const float4*)(Bptr + 4) : z4;
        As[0][(lk + 0) * TS + lr] = f2tf32(av0.x);
        As[0][(lk + 1) * TS + lr] = f2tf32(av0.y);
        As[0][(lk + 2) * TS + lr] = f2tf32(av0.z);
        As[0][(lk + 3) * TS + lr] = f2tf32(av0.w);
        As[0][(lk + 4) * TS + lr] = f2tf32(av1.x);
        As[0][(lk + 5) * TS + lr] = f2tf32(av1.y);
        As[0][(lk + 6) * TS + lr] = f2tf32(av1.z);
        As[0][(lk + 7) * TS + lr] = f2tf32(av1.w);
        Bs[0][(lk + 0) * TS + lr] = f2tf32(bv0.x);
        Bs[0][(lk + 1) * TS + lr] = f2tf32(bv0.y);
        Bs[0][(lk + 2) * TS + lr] = f2tf32(bv0.z);
        Bs[0][(lk + 3) * TS + lr] = f2tf32(bv0.w);
        Bs[0][(lk + 4) * TS + lr] = f2tf32(bv1.x);
        Bs[0][(lk + 5) * TS + lr] = f2tf32(bv1.y);
        Bs[0][(lk + 6) * TS + lr] = f2tf32(bv1.z);
        Bs[0][(lk + 7) * TS + lr] = f2tf32(bv1.w);
    }
    __syncthreads();

    int cur = 0;
    for (int k0 = 0; k0 < K; k0 += BKG) {
        const bool has_next = (k0 + BKG) < K;
        float4 nav0, nav1, nbv0, nbv1;
        if (has_next) {
            nav0 = aval ? *(const float4*)(Aptr + k0 + BKG)     : z4;
            nav1 = aval ? *(const float4*)(Aptr + k0 + BKG + 4) : z4;
            nbv0 = bval ? *(const float4*)(Bptr + k0 + BKG)     : z4;
            nbv1 = bval ? *(const float4*)(Bptr + k0 + BKG + 4) : z4;
        }

#pragma unroll
        for (int half = 0; half < 2; half++) {
            const int kb8 = half * 8;
            uint32_t a[4][4];
#pragma unroll
            for (int ma = 0; ma < 4; ma++) {
                const int base = warp_m + ma * 16 + mr;
                a[ma][0] = As[cur][(kb8 + kr) * TS + base];
                a[ma][1] = As[cur][(kb8 + kr) * TS + base + 8];
                a[ma][2] = As[cur][(kb8 + kr + 4) * TS + base];
                a[ma][3] = As[cur][(kb8 + kr + 4) * TS + base + 8];
            }
            uint32_t b[4][2];
#pragma unroll
            for (int nb = 0; nb < 4; nb++) {
                const int nbase = warp_n + nb * 8 + mr;
                b[nb][0] = Bs[cur][(kb8 + kr) * TS + nbase];
                b[nb][1] = Bs[cur][(kb8 + kr + 4) * TS + nbase];
            }
#pragma unroll
            for (int ma = 0; ma < 4; ma++)
#pragma unroll
                for (int nb = 0; nb < 4; nb++)
                    mma_tf32(acc[ma][nb], a[ma][0], a[ma][1], a[ma][2], a[ma][3],
                             b[nb][0], b[nb][1]);
        }

        if (has_next) {
            const int nxt = cur ^ 1;
            As[nxt][(lk + 0) * TS + lr] = f2tf32(nav0.x);
            As[nxt][(lk + 1) * TS + lr] = f2tf32(nav0.y);
            As[nxt][(lk + 2) * TS + lr] = f2tf32(nav0.z);
            As[nxt][(lk + 3) * TS + lr] = f2tf32(nav0.w);
            As[nxt][(lk + 4) * TS + lr] = f2tf32(nav1.x);
            As[nxt][(lk + 5) * TS + lr] = f2tf32(nav1.y);
            As[nxt][(lk + 6) * TS + lr] = f2tf32(nav1.z);
            As[nxt][(lk + 7) * TS + lr] = f2tf32(nav1.w);
            Bs[nxt][(lk + 0) * TS + lr] = f2tf32(nbv0.x);
            Bs[nxt][(lk + 1) * TS + lr] = f2tf32(nbv0.y);
            Bs[nxt][(lk + 2) * TS + lr] = f2tf32(nbv0.z);
            Bs[nxt][(lk + 3) * TS + lr] = f2tf32(nbv0.w);
            Bs[nxt][(lk + 4) * TS + lr] = f2tf32(nbv1.x);
            Bs[nxt][(lk + 5) * TS + lr] = f2tf32(nbv1.y);
            Bs[nxt][(lk + 6) * TS + lr] = f2tf32(nbv1.z);
            Bs[nxt][(lk + 7) * TS + lr] = f2tf32(nbv1.w);
            __syncthreads();
            cur = nxt;
        }
    }

#pragma unroll
    for (int ma = 0; ma < 4; ma++) {
        const int r = row0 + warp_m + ma * 16 + (lane >> 2);
        if (r >= M) continue;
#pragma unroll
        for (int nb = 0; nb < 4; nb++) {
            const int c = col0 + warp_n + nb * 8 + 2 * (lane & 3);
            if (c < N) {
                float* p0 = C + (size_t)r * N + c;
                p0[0] = acc[ma][nb].x;
                p0[1] = acc[ma][nb].y;
                float* p1 = p0 + (size_t)8 * N;
                p1[0] = acc[ma][nb].z;
                p1[1] = acc[ma][nb].w;
            }
        }
    }
}

// ---------------- RMS norms ----------------
__global__ __launch_bounds__(256) void rms_q_kernel(float* __restrict__ x,
                                                    const float* __restrict__ w) {
    __shared__ float sbuf[256];
    const int row = blockIdx.x;
    float* p = x + (size_t)row * QLR;
    float ss = 0.0f;
    for (int d = threadIdx.x; d < QLR; d += 256) { float v = p[d]; ss += v * v; }
    sbuf[threadIdx.x] = ss;
    __syncthreads();
    if (threadIdx.x == 0) {
        float r = 0.0f;
        for (int i = 0; i < 256; i++) r += sbuf[i];
        sbuf[0] = r;
    }
    __syncthreads();
    const float inv = rsqrtf(sbuf[0] * (1.0f / QLR) + 1e-6f);
    for (int d = threadIdx.x; d < QLR; d += 256) p[d] = p[d] * inv * w[d];
}

__global__ __launch_bounds__(256) void rms_kv_kernel(const float* __restrict__ xin,
                                                     const float* __restrict__ w,
                                                     float* __restrict__ xout) {
    __shared__ float sbuf[256];
    const int row = blockIdx.x;
    const float* p = xin + (size_t)row * (KVLR + ROPEDIM);
    float ss = 0.0f;
    for (int d = threadIdx.x; d < KVLR; d += 256) { float v = p[d]; ss += v * v; }
    sbuf[threadIdx.x] = ss;
    __syncthreads();
    if (threadIdx.x == 0) {
        float r = 0.0f;
        for (int i = 0; i < 256; i++) r += sbuf[i];
        sbuf[0] = r;
    }
    __syncthreads();
    const float inv = rsqrtf(sbuf[0] * (1.0f / KVLR) + 1e-6f);
    float* o = xout + (size_t)row * KVLR;
    for (int d = threadIdx.x; d < KVLR; d += 256) o[d] = p[d] * inv * w[d];
}

// ---------------- RoPE: half-split pairing, NEGATED rotation sign (validated R8)
__device__ __forceinline__ float rope_invfreq(int j) {
    return exp2f(-(float)j * (13.287712379549449f / 32.0f));
}

__global__ void rope_q_kernel(float* __restrict__ q) {
    const int t = blockIdx.x;
    const int h = threadIdx.x >> 5;
    const int j = threadIdx.x & 31;
    float* base = q + (size_t)t * (NH * QHD) + h * QHD + NOPE;
    float c, s;
    sincosf((float)t * rope_invfreq(j), &c, &s);
    const float x0 = base[j];
    const float x1 = base[j + 32];
    base[j]      = x0 * c + x1 * s;
    base[j + 32] = x1 * c - x0 * s;
}

__global__ void rope_k_kernel(const float* __restrict__ kvlatpe, float* __restrict__ kpe) {
    const int t = blockIdx.x;
    const int j = threadIdx.x;
    const float* base = kvlatpe + (size_t)t * (KVLR + ROPEDIM) + KVLR;
    float c, s;
    sincosf((float)t * rope_invfreq(j), &c, &s);
    const float x0 = base[j];
    const float x1 = base[j + 32];
    kpe[(size_t)t * ROPEDIM + j]      = x0 * c + x1 * s;
    kpe[(size_t)t * ROPEDIM + j + 32] = x1 * c - x0 * s;
}

// ---------------- Flash attention: tensor-core S (tf32x2) + PV (tf32) ---------
// Q pre-split into hi/lo tf32 at staging (once per CTA); K split on the fly.
// Qhi/Qlo: uint32 [64][200]; Ks: fp32 [64][200]; Vs: tf32 [64][136]; Ps: fp32 [64][68]
#define FQ 200
#define FV 136
#define FP 68
#define F_QH 0
#define F_QL (F_QH + 64 * FQ)            // 12800
#define F_KS (F_QL + 64 * FQ)            // 25600
#define F_VS (F_KS + 64 * FQ)            // 38400
#define F_PS (F_VS + 64 * FV)            // 47104
#define F_MS (F_PS + 64 * FP)            // 51456
#define F_LS (F_MS + 64)
#define F_CS (F_LS + 64)
#define FLASH_SMEM_WORDS (F_CS + 64)     // 51648
#define FLASH_SMEM_BYTES (FLASH_SMEM_WORDS * 4)

__global__ __launch_bounds__(256) void flash_kernel(const float* __restrict__ q,
                                                    const float* __restrict__ kv,
                                                    const float* __restrict__ kpe,
                                                    float* __restrict__ attn) {
    extern __shared__ __align__(16) float sm[];
    uint32_t* Qhi = (uint32_t*)(sm + F_QH);
    uint32_t* Qlo = (uint32_t*)(sm + F_QL);
    float*    Ks  = sm + F_KS;
    uint32_t* Vs  = (uint32_t*)(sm + F_VS);
    float*    Ps  = sm + F_PS;
    float*    m_s = sm + F_MS;
    float*    l_s = sm + F_LS;
    float*    c_s = sm + F_CS;

    const int tid  = threadIdx.x;
    const int lane = tid & 31;
    const int wid  = tid >> 5;
    const int kr = lane & 3;
    const int mr = lane >> 2;
    const int qb = blockIdx.x;
    const int h  = blockIdx.y;
    const int qbase = qb * 64;
    const float scale = 0.07216878364870323f;  // 192^-0.5

    const int s_wm = (wid & 1) * 32;
    const int s_wn = (wid >> 1) * 16;
    const int p_wm = (wid & 1) * 32;
    const int p_wn = (wid >> 1) * 32;

    // stage Q once: pre-split hi/lo
    for (int idx = tid; idx < 64 * 192; idx += 256) {
        int r = idx / 192, d = idx - r * 192;
        float val = q[(size_t)(qbase + r) * (NH * QHD) + h * QHD + d] * scale;
        uint32_t hi, lo;
        split_tf32(val, hi, lo);
        Qhi[r * FQ + d] = hi;
        Qlo[r * FQ + d] = lo;
    }
    if (tid < 64) { m_s[tid] = -1e30f; l_s[tid] = 0.0f; }

    float4 acc[2][4];
#pragma unroll
    for (int i = 0; i < 2; i++)
#pragma unroll
        for (int j = 0; j < 4; j++) acc[i][j] = make_float4(0.f, 0.f, 0.f, 0.f);

    for (int kb = 0; kb <= qb; kb++) {
        const int kbase = kb * 64;
        __syncthreads();
        for (int idx = tid; idx < 64 * 192; idx += 256) {
            int c = idx / 192, d = idx - c * 192;
            float v = (d < NOPE)
                ? kv[(size_t)(kbase + c) * (NH * (NOPE + VHD)) + h * (NOPE + VHD) + d]
                : kpe[(size_t)(kbase + c) * ROPEDIM + (d - NOPE)];
            Ks[c * FQ + d] = v;
        }
        for (int idx = tid; idx < 64 * 128; idx += 256) {
            int c = idx >> 7, d = idx & 127;
            Vs[c * FV + d] = f2tf32(
                kv[(size_t)(kbase + c) * (NH * (NOPE + VHD)) + h * (NOPE + VHD) + NOPE + d]);
        }
        __syncthreads();

        // ---- S = Q K^T via tf32x2 (hi/lo), fp32 accumulate ----
        float4 sc[2][2];
#pragma unroll
        for (int i = 0; i < 2; i++)
#pragma unroll
            for (int j = 0; j < 2; j++) sc[i][j] = make_float4(0.f, 0.f, 0.f, 0.f);

        for (int k0 = 0; k0 < 192; k0 += 8) {
            uint32_t ah[2][4], al[2][4];
#pragma unroll
            for (int ma = 0; ma < 2; ma++) {
                const int r0 = s_wm + ma * 16 + mr;
                const int b0 = r0 * FQ + k0 + kr;
                ah[ma][0] = Qhi[b0];               al[ma][0] = Qlo[b0];
                ah[ma][1] = Qhi[b0 + 8 * FQ];      al[ma][1] = Qlo[b0 + 8 * FQ];
                ah[ma][2] = Qhi[b0 + 4];           al[ma][2] = Qlo[b0 + 4];
                ah[ma][3] = Qhi[b0 + 8 * FQ + 4];  al[ma][3] = Qlo[b0 + 8 * FQ + 4];
            }
            uint32_t bh[2][2], bl[2][2];
#pragma unroll
            for (int nb = 0; nb < 2; nb++) {
                const int n0 = s_wn + nb * 8 + mr;
                split_tf32(Ks[n0 * FQ + k0 + kr],     bh[nb][0], bl[nb][0]);
                split_tf32(Ks[n0 * FQ + k0 + kr + 4], bh[nb][1], bl[nb][1]);
            }
#pragma unroll
            for (int ma = 0; ma < 2; ma++)
#pragma unroll
                for (int nb = 0; nb < 2; nb++) {
                    mma_tf32(sc[ma][nb], ah[ma][0], ah[ma][1], ah[ma][2], ah[ma][3],
                             bh[nb][0], bh[nb][1]);
                    mma_tf32(sc[ma][nb], al[ma][0], al[ma][1], al[ma][2], al[ma][3],
                             bh[nb][0], bh[nb][1]);
                    mma_tf32(sc[ma][nb], ah[ma][0], ah[ma][1], ah[ma][2], ah[ma][3],
                             bl[nb][0], bl[nb][1]);
                }
        }

        // mask diagonal tile + write scores to Ps
#pragma unroll
        for (int ma = 0; ma < 2; ma++) {
            const int r0 = s_wm + ma * 16 + (lane >> 2);
#pragma unroll
            for (int nb = 0; nb < 2; nb++) {
                const int c0 = s_wn + nb * 8 + 2 * (lane & 3);
                float4 v = sc[ma][nb];
                if (kb == qb) {
                    if (c0 > r0)         v.x = -1e30f;
                    if (c0 + 1 > r0)     v.y = -1e30f;
                    if (c0 > r0 + 8)     v.z = -1e30f;
                    if (c0 + 1 > r0 + 8) v.w = -1e30f;
                }
                Ps[r0 * FP + c0]           = v.x;
                Ps[r0 * FP + c0 + 1]       = v.y;
                Ps[(r0 + 8) * FP + c0]     = v.z;
                Ps[(r0 + 8) * FP + c0 + 1] = v.w;
            }
        }
        __syncthreads();

        // ---- per-row online softmax (serial row scan) ----
        if (tid < 64) {
            const int row = tid;
            float mx = -1e30f;
            for (int c = 0; c < 64; c++) mx = fmaxf(mx, Ps[row * FP + c]);
            float mold = m_s[row];
            float mnew = fmaxf(mold, mx);
            float corr = __expf(mold - mnew);
            float rs = 0.0f;
            for (int c = 0; c < 64; c++) {
                float e = __expf(Ps[row * FP + c] - mnew);
                Ps[row * FP + c] = e;
                rs += e;
            }
            l_s[row] = l_s[row] * corr + rs;
            m_s[row] = mnew;
            c_s[row] = corr;
        }
        __syncthreads();

        // ---- acc = acc*corr + P @ V (single-pass tf32) ----
#pragma unroll
        for (int ma = 0; ma < 2; ma++) {
            const int r0 = p_wm + ma * 16 + (lane >> 2);
            const float c1 = c_s[r0];
            const float c2 = c_s[r0 + 8];
#pragma unroll
            for (int nb = 0; nb < 4; nb++) {
                acc[ma][nb].x *= c1; acc[ma][nb].y *= c1;
                acc[ma][nb].z *= c2; acc[ma][nb].w *= c2;
            }
        }
        for (int k0 = 0; k0 < 64; k0 += 8) {
            uint32_t a[2][4];
#pragma unroll
            for (int ma = 0; ma < 2; ma++) {
                const int r0 = p_wm + ma * 16 + mr;
                a[ma][0] = f2tf32(Ps[r0 * FP + k0 + kr]);
                a[ma][1] = f2tf32(Ps[(r0 + 8) * FP + k0 + kr]);
                a[ma][2] = f2tf32(Ps[r0 * FP + k0 + kr + 4]);
                a[ma][3] = f2tf32(Ps[(r0 + 8) * FP + k0 + kr + 4]);
            }
            uint32_t b[4][2];
#pragma unroll
            for (int nb = 0; nb < 4; nb++) {
                const int n0 = p_wn + nb * 8 + mr;
                b[nb][0] = Vs[(k0 + kr) * FV + n0];
                b[nb][1] = Vs[(k0 + kr + 4) * FV + n0];
            }
#pragma unroll
            for (int ma = 0; ma < 2; ma++)
#pragma unroll
                for (int nb = 0; nb < 4; nb++)
                    mma_tf32(acc[ma][nb], a[ma][0], a[ma][1], a[ma][2], a[ma][3],
                             b[nb][0], b[nb][1]);
        }
    }

    // epilogue: normalize by l and store
#pragma unroll
    for (int ma = 0; ma < 2; ma++) {
        const int r0 = p_wm + ma * 16 + (lane >> 2);
        const float inv1 = 1.0f / l_s[r0];
        const float inv2 = 1.0f / l_s[r0 + 8];
        const int t1 = qbase + r0;
        const int t2 = t1 + 8;
#pragma unroll
        for (int nb = 0; nb < 4; nb++) {
            const int c0 = p_wn + nb * 8 + 2 * (lane & 3);
            float* o1 = attn + (size_t)t1 * (NH * VHD) + h * VHD + c0;
            o1[0] = acc[ma][nb].x * inv1;
            o1[1] = acc[ma][nb].y * inv1;
            float* o2 = attn + (size_t)t2 * (NH * VHD) + h * VHD + c0;
            o2[0] = acc[ma][nb].z * inv2;
            o2[1] = acc[ma][nb].w * inv2;
        }
    }
}

// ---------------- launch ----------------
extern "C" void kernel_launch(void* const* d_in, const int* in_sizes, int n_in,
                              void* d_out, int out_size) {
    const float *hidden = nullptr, *q_a_w = nullptr, *q_a_ln_w = nullptr, *q_b_w = nullptr,
                *kv_a_w = nullptr, *kv_a_ln_w = nullptr, *kv_b_w = nullptr, *o_w = nullptr;
    for (int i = 0; i < n_in; i++) {
        const float* p = (const float*)d_in[i];
        switch (in_sizes[i]) {
            case QLR * HDIM:                q_a_w = p;    break;  // 3145728
            case QLR:                       q_a_ln_w = p; break;  // 1536
            case NH * QHD * QLR:            q_b_w = p;    break;  // 4718592
            case (KVLR + ROPEDIM) * HDIM:   kv_a_w = p;   break;  // 1179648
            case KVLR:                      kv_a_ln_w = p;break;  // 512
            case NH * (NOPE + VHD) * KVLR:  kv_b_w = p;   break;  // 2097152
            case SEQ * HDIM:  if (!hidden) hidden = p; else o_w = p; break; // 4194304 x2
        }
    }
    float* out = (float*)d_out;

    float* base = nullptr;
    cudaGetSymbolAddress((void**)&base, g_scratch);
    float* qlat    = base + OFF_QLAT;
    float* kvlatpe = base + OFF_KVLATPE;
    float* kvlat   = base + OFF_KVLAT;
    float* kpe     = base + OFF_KPE;
    float* qbuf    = base + OFF_Q;
    float* kvbuf   = base + OFF_KV;
    float* attnbuf = base + OFF_ATTN;

    cudaFuncSetAttribute(flash_kernel, cudaFuncAttributeMaxDynamicSharedMemorySize,
                         FLASH_SMEM_BYTES);

    sgemm_tf32<<<dim3(QLR / 128, SEQ / 128), 256>>>(hidden, q_a_w, qlat, SEQ, QLR, HDIM);
    sgemm_tf32<<<dim3((KVLR + ROPEDIM + 127) / 128, SEQ / 128), 256>>>(hidden, kv_a_w, kvlatpe,
                                                                       SEQ, KVLR + ROPEDIM, HDIM);
    rms_q_kernel<<<SEQ, 256>>>(qlat, q_a_ln_w);
    rms_kv_kernel<<<SEQ, 256>>>(kvlatpe, kv_a_ln_w, kvlat);
    rope_k_kernel<<<SEQ, 32>>>(kvlatpe, kpe);
    sgemm_tf32<<<dim3((NH * QHD) / 128, SEQ / 128), 256>>>(qlat, q_b_w, qbuf, SEQ, NH * QHD, QLR);
    sgemm_tf32<<<dim3((NH * (NOPE + VHD)) / 128, SEQ / 128), 256>>>(kvlat, kv_b_w, kvbuf,
                                                                    SEQ, NH * (NOPE + VHD), KVLR);
    rope_q_kernel<<<SEQ, 512>>>(qbuf);
    flash_kernel<<<dim3(SEQ / 64, NH), 256, FLASH_SMEM_BYTES>>>(qbuf, kvbuf, kpe, attnbuf);
    sgemm_tf32<<<dim3(HDIM / 128, SEQ / 128), 256>>>(attnbuf, o_w, out, SEQ, HDIM, NH * VHD);
}